// round 3
// baseline (speedup 1.0000x reference)
#include <cuda_runtime.h>
#include <cstdint>

// Problem constants (fixed by the reference)
#define NN    8192
#define IN_F  256
#define OUT_F 128
#define TI    32      // rows per block (main kernel)
#define TJ    128     // j-tile per iteration

// Scratch (no cudaMalloc allowed) — 4 MB + 32 KB
__device__ float g_Wh[NN * OUT_F];
__device__ float g_s[NN];

// Packed f32x2 FMA (Blackwell): d = a*b + d on two lanes at once
__device__ __forceinline__ void fma2(unsigned long long& d,
                                     unsigned long long a,
                                     unsigned long long b) {
    asm("fma.rn.f32x2 %0, %1, %2, %0;" : "+l"(d) : "l"(a), "l"(b));
}
__device__ __forceinline__ float2 upk(unsigned long long v) {
    float2 r;
    asm("mov.b64 {%0, %1}, %2;" : "=f"(r.x), "=f"(r.y) : "l"(v));
    return r;
}

// ---------------------------------------------------------------------------
// Kernel 1: Wh[i][o] = sum_k h[i][k] * W[o][k]       (8192x128, K=256)
// Block = 128 threads (one per output feature), 32 rows per block.
// h tile staged transposed in SMEM (pad 36 -> conflict-light STS, aligned LDS.128)
// ---------------------------------------------------------------------------
__global__ __launch_bounds__(128) void wh_kernel(const float* __restrict__ h,
                                                 const float* __restrict__ W) {
    __shared__ __align__(16) float hs[IN_F][36];
    const int t  = threadIdx.x;
    const int i0 = blockIdx.x * TI;

    for (int idx = t; idx < TI * IN_F; idx += 128) {
        int i = idx >> 8;          // / 256
        int k = idx & (IN_F - 1);  // % 256
        hs[k][i] = h[(size_t)(i0 + i) * IN_F + k];
    }
    __syncthreads();

    float acc[TI];
#pragma unroll
    for (int i = 0; i < TI; i++) acc[i] = 0.f;

    const float* wr = W + (size_t)t * IN_F;  // thread's W row stays hot in L1
#pragma unroll 4
    for (int k = 0; k < IN_F; k++) {
        float wv = wr[k];
#pragma unroll
        for (int i = 0; i < TI; i += 4) {
            float4 hv = *(const float4*)&hs[k][i];   // broadcast LDS.128
            acc[i + 0] = fmaf(wv, hv.x, acc[i + 0]);
            acc[i + 1] = fmaf(wv, hv.y, acc[i + 1]);
            acc[i + 2] = fmaf(wv, hv.z, acc[i + 2]);
            acc[i + 3] = fmaf(wv, hv.w, acc[i + 3]);
        }
    }
#pragma unroll
    for (int i = 0; i < TI; i++)
        g_Wh[(size_t)(i0 + i) * OUT_F + t] = acc[i];
}

// ---------------------------------------------------------------------------
// Kernel 2: s[i] = sum_o Wh[i][o] * a[o]   — one warp per row
// ---------------------------------------------------------------------------
__global__ void s_kernel(const float* __restrict__ a) {
    int gid  = blockIdx.x * blockDim.x + threadIdx.x;
    int row  = gid >> 5;
    int lane = gid & 31;
    if (row >= NN) return;
    const float* wh = g_Wh + (size_t)row * OUT_F;
    float sum = 0.f;
#pragma unroll
    for (int m = 0; m < OUT_F / 32; m++)
        sum += wh[lane + 32 * m] * a[lane + 32 * m];
#pragma unroll
    for (int off = 16; off; off >>= 1)
        sum += __shfl_xor_sync(0xffffffffu, sum, off);
    if (lane == 0) g_s[row] = sum;
}

// ---------------------------------------------------------------------------
// Kernel 3 (dominant): fused masked-softmax aggregation + LayerNorm.
//   w[i][j] = adj[i][j] ? exp(lrelu(s_i + s_j)) : 0
//   hp[i]   = (sum_j w[i][j] * Wh[j]) / (sum_j w[i][j])
//   out[i]  = LN(hp[i]) * gamma + beta
//
// Block: 128 threads, TI=32 rows.
//   thread t: feature group fg = t&31 (4 features = one float4 of Wh),
//             row group    wg = t>>5 (8 rows), 16 f32x2 accumulators.
// Per j-tile: phase 1 — thread t computes weights for column j0+t, all 32 rows,
//             stored DUPLICATED as (w,w) float2 in SMEM (stride 34 -> mild STS
//             conflicts, 16B-aligned rows for LDS.128 broadcast in phase 2).
//             phase 2 — 1 LDG.128 (Wh, coalesced) + 4 LDS.128 + 16 FFMA2 per j.
// ---------------------------------------------------------------------------
__global__ __launch_bounds__(128) void gat_kernel(const int*   __restrict__ adj,
                                                  const float* __restrict__ gamma,
                                                  const float* __restrict__ beta,
                                                  float*       __restrict__ out) {
    __shared__ __align__(16) float2 wsh[TJ * 34];   // [jj][i] duplicated weights
    __shared__ float si_s[TI];
    __shared__ float dinv_s[TI];

    const int t  = threadIdx.x;
    const int i0 = blockIdx.x * TI;
    const int fg = t & 31;
    const int wg = t >> 5;
    const int r0 = wg * 8;

    if (t < TI) si_s[t] = g_s[i0 + t];
    __syncthreads();

    unsigned long long acc[16];
#pragma unroll
    for (int k = 0; k < 16; k++) acc[k] = 0ull;
    float dpart[TI];
#pragma unroll
    for (int i = 0; i < TI; i++) dpart[i] = 0.f;

    for (int j0 = 0; j0 < NN; j0 += TJ) {
        // ---- phase 1: weights for column j = j0 + t (coalesced adj stream) ----
        {
            float sj = g_s[j0 + t];
            const int* ap = adj + (size_t)i0 * NN + (j0 + t);
            float2* wc = wsh + t * 34;
#pragma unroll
            for (int i = 0; i < TI; i++) {
                int   av = ap[(size_t)i * NN];
                float e  = si_s[i] + sj;
                e        = (e > 0.f) ? e : 0.2f * e;       // LeakyReLU(0.2)
                float w  = av ? __expf(e) : 0.f;            // mask -> exp -> 0
                dpart[i] += w;
                wc[i] = make_float2(w, w);                  // pre-duplicated
            }
        }
        __syncthreads();

        // ---- phase 2: rank-TJ update of the 32x128 accumulator tile ----
        const float* xb = g_Wh + (size_t)j0 * OUT_F + fg * 4;
#pragma unroll 2
        for (int jj = 0; jj < TJ; jj++) {
            ulonglong2 x = *(const ulonglong2*)(xb + (size_t)jj * OUT_F);
            const ulonglong2* wp = (const ulonglong2*)(wsh + jj * 34 + r0);
            ulonglong2 w01 = wp[0];
            ulonglong2 w23 = wp[1];
            ulonglong2 w45 = wp[2];
            ulonglong2 w67 = wp[3];
            fma2(acc[0],  w01.x, x.x);  fma2(acc[1],  w01.x, x.y);
            fma2(acc[2],  w01.y, x.x);  fma2(acc[3],  w01.y, x.y);
            fma2(acc[4],  w23.x, x.x);  fma2(acc[5],  w23.x, x.y);
            fma2(acc[6],  w23.y, x.x);  fma2(acc[7],  w23.y, x.y);
            fma2(acc[8],  w45.x, x.x);  fma2(acc[9],  w45.x, x.y);
            fma2(acc[10], w45.y, x.x);  fma2(acc[11], w45.y, x.y);
            fma2(acc[12], w67.x, x.x);  fma2(acc[13], w67.x, x.y);
            fma2(acc[14], w67.y, x.x);  fma2(acc[15], w67.y, x.y);
        }
        __syncthreads();
    }

    // ---- denominator: reduce dpart over the 128 threads ----
    float* red = (float*)wsh;   // 128*33 floats fits easily in wsh
#pragma unroll
    for (int i = 0; i < TI; i++) red[t * 33 + i] = dpart[i];
    __syncthreads();
    if (t < TI) {
        float d = 0.f;
        for (int tt = 0; tt < 128; tt++) d += red[tt * 33 + t];
        dinv_s[t] = 1.0f / d;
    }
    __syncthreads();

    // ---- epilogue: divide + LayerNorm (warp wg owns rows r0..r0+7 fully) ----
    const float4 gm = *(const float4*)(gamma + fg * 4);
    const float4 bt = *(const float4*)(beta + fg * 4);
#pragma unroll
    for (int r = 0; r < 8; r++) {
        const int i = r0 + r;
        float inv = dinv_s[i];
        float2 v0 = upk(acc[2 * r]);
        float2 v1 = upk(acc[2 * r + 1]);
        v0.x *= inv; v0.y *= inv; v1.x *= inv; v1.y *= inv;

        float sm = v0.x + v0.y + v1.x + v1.y;
        float sq = v0.x * v0.x + v0.y * v0.y + v1.x * v1.x + v1.y * v1.y;
#pragma unroll
        for (int off = 16; off; off >>= 1) {
            sm += __shfl_xor_sync(0xffffffffu, sm, off);
            sq += __shfl_xor_sync(0xffffffffu, sq, off);
        }
        float mean = sm * (1.0f / OUT_F);
        float var  = sq * (1.0f / OUT_F) - mean * mean;
        float rstd = rsqrtf(var + 1e-5f);

        float4 o;
        o.x = (v0.x - mean) * rstd * gm.x + bt.x;
        o.y = (v0.y - mean) * rstd * gm.y + bt.y;
        o.z = (v1.x - mean) * rstd * gm.z + bt.z;
        o.w = (v1.y - mean) * rstd * gm.w + bt.w;
        *(float4*)(out + (size_t)(i0 + i) * OUT_F + fg * 4) = o;
    }
}

// ---------------------------------------------------------------------------
// Launch: inputs in metadata order: h, adj, W, a, gamma, beta
// ---------------------------------------------------------------------------
extern "C" void kernel_launch(void* const* d_in, const int* in_sizes, int n_in,
                              void* d_out, int out_size) {
    const float* h     = (const float*)d_in[0];
    const int*   adj   = (const int*)  d_in[1];
    const float* W     = (const float*)d_in[2];
    const float* a     = (const float*)d_in[3];
    const float* gamma = (const float*)d_in[4];
    const float* beta  = (const float*)d_in[5];
    float* out = (float*)d_out;

    wh_kernel<<<NN / TI, 128>>>(h, W);
    s_kernel<<<(NN * 32) / 256, 256>>>(a);
    gat_kernel<<<NN / TI, 128>>>(adj, gamma, beta, out);
}

// round 5
// speedup vs baseline: 5.0373x; 5.0373x over previous
#include <cuda_runtime.h>
#include <cuda_fp16.h>
#include <cstdint>

// ============================================================================
// Problem constants
// ============================================================================
#define NN    8192
#define IN_F  256
#define F     128          // OUT_F
#define MT    64           // rows per CTA (main kernel)
#define KC    128          // j-chunk
#define NCHUNK (NN / KC)
#define NF    136          // feature rows incl. denominator row (128) + zero pad

// ============================================================================
// Scratch globals (no cudaMalloc allowed)
// ============================================================================
__device__ float  g_Wh[NN * F];      // 4 MB
__device__ float  g_s[NN];
__device__ __half g_sh[NN];
__device__ float  g_e1[NN];          // exp(s)
__device__ float  g_e2[NN];          // exp(0.2 s)
__device__ __half g_Y1[NF * NN];     // [f][j]: f<128: e1_j*Wh[j][f]; f=128: e1_j; else 0
__device__ __half g_Y2[NF * NN];     // same with e2

// ============================================================================
// SMEM layout (main kernel) — tile rows padded to 136 halves (272 B)
// ============================================================================
#define TSTR  272                    // bytes per tile row (136 halves)
#define SP    0                      // P mask tile   64 x 136 f16  = 17408 B
#define SQ    17408                  // Q mask tile                 = 17408 B
#define SY1   34816                  // Y1 tile      136 x 136 f16  = 36992 B
#define SY2   71808                  // Y2 tile                     = 36992 B
#define OFF_SJH 108800               // 128 half
#define OFF_SIH 109056               // 64 half
#define OFF_E1  109184               // 64 f32
#define OFF_E2  109440               // 64 f32
#define OFF_GM  109696               // 128 f32
#define OFF_BT  110208               // 128 f32
#define SMEM_TOT 110720
#define USTR 140                     // floats per row of epilogue buffer u (overlays tiles)

// ============================================================================
// PTX helpers (all base-sm_100 legal: ldmatrix / mma.sync / cp.async)
// ============================================================================
__device__ __forceinline__ uint32_t smem_u32(const void* p) {
    uint32_t a;
    asm("{ .reg .u64 t; cvta.to.shared.u64 t, %1; cvt.u32.u64 %0, t; }"
        : "=r"(a) : "l"(p));
    return a;
}
__device__ __forceinline__ void ldsm4(uint32_t* r, uint32_t addr) {
    asm volatile("ldmatrix.sync.aligned.m8n8.x4.shared.b16 {%0,%1,%2,%3}, [%4];"
                 : "=r"(r[0]), "=r"(r[1]), "=r"(r[2]), "=r"(r[3]) : "r"(addr));
}
__device__ __forceinline__ void ldsm2(uint32_t* r, uint32_t addr) {
    asm volatile("ldmatrix.sync.aligned.m8n8.x2.shared.b16 {%0,%1}, [%2];"
                 : "=r"(r[0]), "=r"(r[1]) : "r"(addr));
}
__device__ __forceinline__ void mma16816(float* d, const uint32_t* a,
                                         uint32_t b0, uint32_t b1) {
    asm volatile(
        "mma.sync.aligned.m16n8k16.row.col.f32.f16.f16.f32 "
        "{%0,%1,%2,%3},{%4,%5,%6,%7},{%8,%9},{%0,%1,%2,%3};"
        : "+f"(d[0]), "+f"(d[1]), "+f"(d[2]), "+f"(d[3])
        : "r"(a[0]), "r"(a[1]), "r"(a[2]), "r"(a[3]), "r"(b0), "r"(b1));
}
__device__ __forceinline__ void cpasync16(uint32_t dst, const void* src) {
    asm volatile("cp.async.cg.shared.global [%0], [%1], 16;" :: "r"(dst), "l"(src)
                 : "memory");
}
__device__ __forceinline__ void cpasync_commit() {
    asm volatile("cp.async.commit_group;" ::: "memory");
}
__device__ __forceinline__ void cpasync_wait0() {
    asm volatile("cp.async.wait_group 0;" ::: "memory");
}
__device__ __forceinline__ uint32_t h2u(__half2 v) {
    union { __half2 h; uint32_t u; } x; x.h = v; return x.u;
}

// ============================================================================
// Kernel 1: Wh = h @ W^T
// ============================================================================
#define WH_TI 16
__global__ __launch_bounds__(128) void wh_kernel(const float* __restrict__ h,
                                                 const float* __restrict__ W) {
    __shared__ __align__(16) float hs[IN_F][20];
    const int t  = threadIdx.x;
    const int i0 = blockIdx.x * WH_TI;

    for (int idx = t; idx < WH_TI * IN_F; idx += 128) {
        int i = idx >> 8;
        int k = idx & (IN_F - 1);
        hs[k][i] = h[(size_t)(i0 + i) * IN_F + k];
    }
    __syncthreads();

    float acc[WH_TI];
#pragma unroll
    for (int i = 0; i < WH_TI; i++) acc[i] = 0.f;

    const float* wr = W + (size_t)t * IN_F;
#pragma unroll 4
    for (int k = 0; k < IN_F; k++) {
        float wv = wr[k];
#pragma unroll
        for (int i = 0; i < WH_TI; i += 4) {
            float4 hv = *(const float4*)&hs[k][i];
            acc[i + 0] = fmaf(wv, hv.x, acc[i + 0]);
            acc[i + 1] = fmaf(wv, hv.y, acc[i + 1]);
            acc[i + 2] = fmaf(wv, hv.z, acc[i + 2]);
            acc[i + 3] = fmaf(wv, hv.w, acc[i + 3]);
        }
    }
#pragma unroll
    for (int i = 0; i < WH_TI; i++)
        g_Wh[(size_t)(i0 + i) * F + t] = acc[i];
}

// ============================================================================
// Kernel 2: s = Wh @ a^T ; derived scalars
// ============================================================================
__global__ void s_kernel(const float* __restrict__ a) {
    int gid  = blockIdx.x * blockDim.x + threadIdx.x;
    int row  = gid >> 5;
    int lane = gid & 31;
    if (row >= NN) return;
    const float* wh = g_Wh + (size_t)row * F;
    float sum = 0.f;
#pragma unroll
    for (int m = 0; m < F / 32; m++)
        sum += wh[lane + 32 * m] * a[lane + 32 * m];
#pragma unroll
    for (int off = 16; off; off >>= 1)
        sum += __shfl_xor_sync(0xffffffffu, sum, off);
    if (lane == 0) {
        g_s[row]  = sum;
        g_sh[row] = __float2half(sum);
        g_e1[row] = __expf(sum);
        g_e2[row] = __expf(0.2f * sum);
    }
}

// ============================================================================
// Kernel 3: build Y1/Y2 [f][j] fp16 with denominator row f=128, zeros 129..135
// ============================================================================
__global__ __launch_bounds__(256) void prep_kernel() {
    __shared__ float whs[32][129];
    __shared__ float e1s[32], e2s[32];
    const int t  = threadIdx.x;
    const int i0 = blockIdx.x * 32;

    for (int idx = t; idx < 32 * F; idx += 256) {
        int i = idx >> 7;
        int f = idx & 127;
        whs[i][f] = g_Wh[(size_t)(i0 + i) * F + f];
    }
    if (t < 32) { e1s[t] = g_e1[i0 + t]; e2s[t] = g_e2[i0 + t]; }
    __syncthreads();

    for (int idx = t; idx < 32 * NF; idx += 256) {
        int f = idx >> 5;
        int i = idx & 31;
        float v1, v2;
        if (f < F)        { float v = whs[i][f]; v1 = e1s[i] * v; v2 = e2s[i] * v; }
        else if (f == F)  { v1 = e1s[i]; v2 = e2s[i]; }
        else              { v1 = 0.f; v2 = 0.f; }
        g_Y1[(size_t)f * NN + i0 + i] = __float2half(v1);
        g_Y2[(size_t)f * NN + i0 + i] = __float2half(v2);
    }
}

// ============================================================================
// Kernel 4 (main): dual masked GEMM on HMMA + softmax-normalize + LayerNorm
//  - P[i,j] = (adj & s_i+s_j>0), Q[i,j] = (adj & !(...)), both fp16 {0,1}
//  - D1 = P@Y1^T, D2 = Q@Y2^T  (fp32 accum; col 128 = denominators)
//  - u = e^{s_i} D1 + e^{0.2 s_i} D2 ; out = LN(u[:, :128] / u[:,128])
// 8 warps: warp = (m-slice ms=wid&3 [16 rows], n-half nh=wid>>2 [72/64 feats])
// ============================================================================
__global__ __launch_bounds__(256, 1) void gat_kernel(const int*   __restrict__ adj,
                                                     const float* __restrict__ gamma,
                                                     const float* __restrict__ beta,
                                                     float*       __restrict__ out) {
    extern __shared__ char smem[];
    const uint32_t sb = smem_u32(smem);

    const int t    = threadIdx.x;
    const int lane = t & 31;
    const int wid  = t >> 5;
    const int ms   = wid & 3;
    const int nh   = wid >> 2;
    const int i0   = blockIdx.x * MT;

    __half* sjh = (__half*)(smem + OFF_SJH);
    __half* sih = (__half*)(smem + OFF_SIH);
    float*  e1s = (float*)(smem + OFF_E1);
    float*  e2s = (float*)(smem + OFF_E2);
    float*  gms = (float*)(smem + OFF_GM);
    float*  bts = (float*)(smem + OFF_BT);

    if (t < 64) {
        sih[t] = g_sh[i0 + t];
        e1s[t] = g_e1[i0 + t];
        e2s[t] = g_e2[i0 + t];
    }
    if (t < 128) { gms[t] = gamma[t]; bts[t] = beta[t]; }

    // accumulators: 9 n-tiles (nh=0 uses 9, nh=1 uses 8) x 2 GEMMs
    float acc1[9][4], acc2[9][4];
#pragma unroll
    for (int n = 0; n < 9; n++)
#pragma unroll
        for (int k = 0; k < 4; k++) { acc1[n][k] = 0.f; acc2[n][k] = 0.f; }
    const int NTN = (nh == 0) ? 9 : 8;

    // build-phase indices: thread -> row brow (4 threads/row), 32-col span
    const int brow  = t >> 2;
    const int q     = t & 3;
    const int jbase = q * 32;
    const uint32_t prow = sb + SP + brow * TSTR + jbase * 2;
    const uint32_t qrow = sb + SQ + brow * TSTR + jbase * 2;

    // mma-phase addresses
    const uint32_t rA    = (uint32_t)(ms * 16 + (lane & 15));
    const uint32_t aOff  = rA * TSTR + (((lane >> 4) & 1) * 8) * 2;
    const uint32_t kBoff = (((lane >> 3) & 1) * 8) * 2;
    uint32_t nB[4];
#pragma unroll
    for (int np = 0; np < 4; np++)
        nB[np] = (uint32_t)(nh * 72 + np * 16 + ((lane >> 4) & 1) * 8 + (lane & 7));
    const uint32_t n8 = (uint32_t)(64 + (lane & 7));   // tail tile (nh==0 only)

    const __half2 z2 = __float2half2_rn(0.f);
    __syncthreads();
    const __half2 si2 = __half2half2(sih[brow]);

    for (int c = 0; c < NCHUNK; c++) {
        const int j0 = c * KC;
        __syncthreads();   // prior MMA reads done before overwriting tiles

        // stage per-chunk sj (halves)
        if (t < KC) sjh[t] = g_sh[j0 + t];

        // async-stage Y tiles (overlaps with mask build)
        {
            const __half* y1 = g_Y1 + j0;
            const __half* y2 = g_Y2 + j0;
            for (int idx = t; idx < NF * 16; idx += 256) {
                int fr = idx >> 4, c16 = idx & 15;
                uint32_t d = fr * TSTR + c16 * 16;
                cpasync16(sb + SY1 + d, (const char*)(y1 + (size_t)fr * NN) + c16 * 16);
                cpasync16(sb + SY2 + d, (const char*)(y2 + (size_t)fr * NN) + c16 * 16);
            }
            cpasync_commit();
        }
        __syncthreads();   // sjh visible

        // ---- mask build: 8 int4 per thread (32 pairs) ----
        {
            const int4* ap = (const int4*)(adj + (size_t)(i0 + brow) * NN + j0 + jbase);
            const __half2* sj2p = (const __half2*)(sjh + jbase);
            __half2 sjv[16];
#pragma unroll
            for (int i = 0; i < 16; i++) sjv[i] = sj2p[i];
#pragma unroll
            for (int k = 0; k < 8; k++) {
                int4 av = ap[k];
                uint32_t p01 = __byte_perm((uint32_t)av.x, (uint32_t)av.y, 0x5410);
                uint32_t p23 = __byte_perm((uint32_t)av.z, (uint32_t)av.w, 0x5410);
                uint32_t m01 = p01 * 0xFFFFu;
                uint32_t m23 = p23 * 0xFFFFu;
                uint32_t g01 = h2u(__hgt2(__hadd2(si2, sjv[2 * k]),     z2));
                uint32_t g23 = h2u(__hgt2(__hadd2(si2, sjv[2 * k + 1]), z2));
                uint32_t P01 = g01 & m01, P23 = g23 & m23;
                uint32_t Q01 = ~g01 & m01 & 0x3C003C00u;
                uint32_t Q23 = ~g23 & m23 & 0x3C003C00u;
                *(uint2*)(smem + (SP + brow * TSTR + (jbase + 4 * k) * 2)) = make_uint2(P01, P23);
                *(uint2*)(smem + (SQ + brow * TSTR + (jbase + 4 * k) * 2)) = make_uint2(Q01, Q23);
            }
        }
        cpasync_wait0();
        __syncthreads();   // tiles ready

        // ---- MMA: 8 k-steps x (P@Y1, Q@Y2) ----
#pragma unroll 1
        for (int ks = 0; ks < 8; ks++) {
            const uint32_t kbyte = ks * 32;
            uint32_t aR[4], b[4];
            // GEMM 1: P @ Y1
            ldsm4(aR, sb + SP + aOff + kbyte);
#pragma unroll
            for (int np = 0; np < 4; np++) {
                ldsm4(b, sb + SY1 + nB[np] * TSTR + kbyte + kBoff);
                mma16816(acc1[2 * np],     aR, b[0], b[1]);
                mma16816(acc1[2 * np + 1], aR, b[2], b[3]);
            }
            if (nh == 0) {
                ldsm2(b, sb + SY1 + n8 * TSTR + kbyte + kBoff);
                mma16816(acc1[8], aR, b[0], b[1]);
            }
            // GEMM 2: Q @ Y2
            ldsm4(aR, sb + SQ + aOff + kbyte);
#pragma unroll
            for (int np = 0; np < 4; np++) {
                ldsm4(b, sb + SY2 + nB[np] * TSTR + kbyte + kBoff);
                mma16816(acc2[2 * np],     aR, b[0], b[1]);
                mma16816(acc2[2 * np + 1], aR, b[2], b[3]);
            }
            if (nh == 0) {
                ldsm2(b, sb + SY2 + n8 * TSTR + kbyte + kBoff);
                mma16816(acc2[8], aR, b[0], b[1]);
            }
        }
    }

    // ---- stage u = a1*D1 + a2*D2 into SMEM (overlays tiles) ----
    __syncthreads();
    float* u = (float*)smem;
    {
        const int r0 = ms * 16 + (lane >> 2);
        const int r1 = r0 + 8;
        const int cb = nh * 72 + (lane & 3) * 2;
        const float a10 = e1s[r0], a20 = e2s[r0];
        const float a11 = e1s[r1], a21 = e2s[r1];
#pragma unroll
        for (int nt = 0; nt < 9; nt++) {
            if (nt >= NTN) break;
            int cc = cb + nt * 8;
            float2 v0, v1;
            v0.x = a10 * acc1[nt][0] + a20 * acc2[nt][0];
            v0.y = a10 * acc1[nt][1] + a20 * acc2[nt][1];
            v1.x = a11 * acc1[nt][2] + a21 * acc2[nt][2];
            v1.y = a11 * acc1[nt][3] + a21 * acc2[nt][3];
            *(float2*)&u[r0 * USTR + cc] = v0;
            *(float2*)&u[r1 * USTR + cc] = v1;
        }
    }
    __syncthreads();

    // ---- LayerNorm: 4 threads per row, each owns 32 features ----
    {
        const int row = t >> 2;
        const int qq  = t & 3;
        const float* ur = u + row * USTR;
        const float inv = 1.0f / ur[128];
        float sm = 0.f, sq = 0.f;
        float4 vv[8];
#pragma unroll
        for (int w = 0; w < 8; w++) {
            float4 v = *(const float4*)&ur[qq * 32 + w * 4];
            v.x *= inv; v.y *= inv; v.z *= inv; v.w *= inv;
            vv[w] = v;
            sm += v.x + v.y + v.z + v.w;
            sq += v.x * v.x + v.y * v.y + v.z * v.z + v.w * v.w;
        }
#pragma unroll
        for (int off = 1; off <= 2; off <<= 1) {
            sm += __shfl_xor_sync(0xffffffffu, sm, off);
            sq += __shfl_xor_sync(0xffffffffu, sq, off);
        }
        const float mean = sm * (1.0f / F);
        const float var  = sq * (1.0f / F) - mean * mean;
        const float rstd = rsqrtf(var + 1e-5f);
        float* orow = out + (size_t)(i0 + row) * F + qq * 32;
#pragma unroll
        for (int w = 0; w < 8; w++) {
            int fb = qq * 32 + w * 4;
            float4 o;
            o.x = (vv[w].x - mean) * rstd * gms[fb + 0] + bts[fb + 0];
            o.y = (vv[w].y - mean) * rstd * gms[fb + 1] + bts[fb + 1];
            o.z = (vv[w].z - mean) * rstd * gms[fb + 2] + bts[fb + 2];
            o.w = (vv[w].w - mean) * rstd * gms[fb + 3] + bts[fb + 3];
            *(float4*)&orow[w * 4] = o;
        }
    }
}

// ============================================================================
// Launch: inputs in metadata order: h, adj, W, a, gamma, beta
// ============================================================================
extern "C" void kernel_launch(void* const* d_in, const int* in_sizes, int n_in,
                              void* d_out, int out_size) {
    const float* h     = (const float*)d_in[0];
    const int*   adj   = (const int*)  d_in[1];
    const float* W     = (const float*)d_in[2];
    const float* a     = (const float*)d_in[3];
    const float* gamma = (const float*)d_in[4];
    const float* beta  = (const float*)d_in[5];
    float* out = (float*)d_out;

    cudaFuncSetAttribute(gat_kernel, cudaFuncAttributeMaxDynamicSharedMemorySize,
                         SMEM_TOT);

    wh_kernel<<<NN / WH_TI, 128>>>(h, W);
    s_kernel<<<(NN * 32) / 256, 256>>>(a);
    prep_kernel<<<NN / 32, 256>>>();
    gat_kernel<<<NN / MT, 256, SMEM_TOT>>>(adj, gamma, beta, out);
}

// round 7
// speedup vs baseline: 7.3786x; 1.4648x over previous
#include <cuda_runtime.h>
#include <cuda_fp16.h>
#include <cstdint>

// ============================================================================
// Problem constants
// ============================================================================
#define NN    8192
#define IN_F  256
#define F     128          // OUT_F
#define MT    64           // rows per CTA (main kernel)
#define KC    128          // j-chunk
#define NCHUNK (NN / KC)
#define NF    136          // B rows: 128 features + ones row (128) + zero pad

// ============================================================================
// Scratch globals (no cudaMalloc allowed) — all 16B-aligned: read via
// uint32_t*/cp.async paths that require >2B alignment.
// ============================================================================
__device__ __align__(16) __half g_sh[NN];     // fp16(s)
__device__ __align__(16) float  g_e1[NN];     // exp(s)       (fp32, epilogue)
__device__ __align__(16) float  g_e2[NN];     // exp(0.2 s)
__device__ __align__(16) __half g_ej1h[NN];   // fp16(exp(s))      (A scaling)
__device__ __align__(16) __half g_ej2h[NN];   // fp16(exp(0.2 s))
__device__ __align__(16) __half g_Y[NF * NN]; // [f][j]: f<128 Wh^T; f=128 ones; pad 0

// ============================================================================
// SMEM layout (gat kernel) — tile rows 136 halves (272 B), double buffered
// ============================================================================
#define TSTR  272
#define SP    0                       // A1 tile  64 x 136 f16  = 17408 B
#define SQ    17408                   // A2 tile                = 17408 B
#define SY    34816                   // B  tile 136 x 136 f16  = 36992 B
#define BUFSZ 71808
#define OFF_E1  (2 * BUFSZ)           // 64 f32
#define OFF_E2  (OFF_E1 + 256)
#define OFF_GM  (OFF_E2 + 256)        // 128 f32
#define OFF_BT  (OFF_GM + 512)
#define SMEM_TOT (OFF_BT + 512)
#define USTR 140                      // epilogue buffer row stride (floats)

// ============================================================================
// PTX helpers (base sm_100 legal)
// ============================================================================
__device__ __forceinline__ uint32_t smem_u32(const void* p) {
    uint32_t a;
    asm("{ .reg .u64 t; cvta.to.shared.u64 t, %1; cvt.u32.u64 %0, t; }"
        : "=r"(a) : "l"(p));
    return a;
}
__device__ __forceinline__ void ldsm4(uint32_t* r, uint32_t addr) {
    asm volatile("ldmatrix.sync.aligned.m8n8.x4.shared.b16 {%0,%1,%2,%3}, [%4];"
                 : "=r"(r[0]), "=r"(r[1]), "=r"(r[2]), "=r"(r[3]) : "r"(addr));
}
__device__ __forceinline__ void ldsm2(uint32_t* r, uint32_t addr) {
    asm volatile("ldmatrix.sync.aligned.m8n8.x2.shared.b16 {%0,%1}, [%2];"
                 : "=r"(r[0]), "=r"(r[1]) : "r"(addr));
}
__device__ __forceinline__ void mma16816(float* d, const uint32_t* a,
                                         uint32_t b0, uint32_t b1) {
    asm volatile(
        "mma.sync.aligned.m16n8k16.row.col.f32.f16.f16.f32 "
        "{%0,%1,%2,%3},{%4,%5,%6,%7},{%8,%9},{%0,%1,%2,%3};"
        : "+f"(d[0]), "+f"(d[1]), "+f"(d[2]), "+f"(d[3])
        : "r"(a[0]), "r"(a[1]), "r"(a[2]), "r"(a[3]), "r"(b0), "r"(b1));
}
__device__ __forceinline__ void cpasync16(uint32_t dst, const void* src) {
    asm volatile("cp.async.cg.shared.global [%0], [%1], 16;" :: "r"(dst), "l"(src)
                 : "memory");
}
__device__ __forceinline__ void cpasync_commit() {
    asm volatile("cp.async.commit_group;" ::: "memory");
}
__device__ __forceinline__ void cpasync_wait0() {
    asm volatile("cp.async.wait_group 0;" ::: "memory");
}
__device__ __forceinline__ uint32_t h2u(__half2 v) {
    union { __half2 h; uint32_t u; } x; x.h = v; return x.u;
}
__device__ __forceinline__ __half2 u2h(uint32_t v) {
    union { __half2 h; uint32_t u; } x; x.u = v; return x.h;
}

// ============================================================================
// Kernel 1 (fused prep): Wh = h @ W^T ; s = Wh @ a^T ; scalars ; Y tile
// Block = 256 threads, 32 rows. W streamed through SMEM in k-blocks of 64.
// hs stride = 36 floats (144 B, 16B multiple -> aligned LDS.128).
// ============================================================================
#define P_HS   0                               // hs  [64][36]  f32 = 9216 B
#define P_WS   9216                            // Ws  [128][65] f32 = 33280 B
#define P_WHS  (P_WS + 33280)                  // whs [32][133] f32 = 17024 B
#define P_A    (P_WHS + 17024)                 // a   [128] f32
#define P_TOT  (P_A + 512)

__global__ __launch_bounds__(256) void prep_kernel(const float* __restrict__ h,
                                                   const float* __restrict__ W,
                                                   const float* __restrict__ a) {
    extern __shared__ char psm[];
    float* hs  = (float*)(psm + P_HS);    // [kk][i]  stride 36
    float* Ws  = (float*)(psm + P_WS);    // [f][kk]  stride 65
    float* whs = (float*)(psm + P_WHS);   // [i][f]   stride 133
    float* as_ = (float*)(psm + P_A);

    const int t  = threadIdx.x;
    const int i0 = blockIdx.x * 32;
    const int f  = t & 127;
    const int hf = t >> 7;                // 0/1 -> rows hf*16 .. +15

    if (t < 128) as_[t] = a[t];

    float acc[16];
#pragma unroll
    for (int i = 0; i < 16; i++) acc[i] = 0.f;

    for (int kb = 0; kb < IN_F; kb += 64) {
        __syncthreads();
        for (int idx = t; idx < 32 * 64; idx += 256) {
            int i = idx >> 6, kk = idx & 63;
            hs[kk * 36 + i] = h[(size_t)(i0 + i) * IN_F + kb + kk];
        }
        for (int idx = t; idx < 128 * 64; idx += 256) {
            int ff = idx >> 6, kk = idx & 63;
            Ws[ff * 65 + kk] = W[(size_t)ff * IN_F + kb + kk];
        }
        __syncthreads();
#pragma unroll 4
        for (int kk = 0; kk < 64; kk++) {
            float wv = Ws[f * 65 + kk];
            const float* hv = &hs[kk * 36 + hf * 16];
#pragma unroll
            for (int i = 0; i < 16; i += 4) {
                float4 v = *(const float4*)&hv[i];
                acc[i + 0] = fmaf(wv, v.x, acc[i + 0]);
                acc[i + 1] = fmaf(wv, v.y, acc[i + 1]);
                acc[i + 2] = fmaf(wv, v.z, acc[i + 2]);
                acc[i + 3] = fmaf(wv, v.w, acc[i + 3]);
            }
        }
    }
    __syncthreads();
#pragma unroll
    for (int i = 0; i < 16; i++)
        whs[(hf * 16 + i) * 133 + f] = acc[i];
    __syncthreads();

    // s per row (warp w -> rows 4w..4w+3), then derived scalars
    {
        const int wid  = t >> 5;
        const int lane = t & 31;
#pragma unroll
        for (int r = 0; r < 4; r++) {
            int row = wid * 4 + r;
            float sum = 0.f;
#pragma unroll
            for (int m = 0; m < 4; m++)
                sum += whs[row * 133 + lane + 32 * m] * as_[lane + 32 * m];
#pragma unroll
            for (int off = 16; off; off >>= 1)
                sum += __shfl_xor_sync(0xffffffffu, sum, off);
            if (lane == 0) {
                float e1 = __expf(sum);
                float e2 = __expf(0.2f * sum);
                g_sh[i0 + row]   = __float2half(sum);
                g_e1[i0 + row]   = e1;
                g_e2[i0 + row]   = e2;
                g_ej1h[i0 + row] = __float2half(e1);
                g_ej2h[i0 + row] = __float2half(e2);
            }
        }
    }

    // Y tile: g_Y[f][i0+i]
    for (int idx = t; idx < NF * 32; idx += 256) {
        int ff = idx >> 5, i = idx & 31;
        float v = (ff < F) ? whs[i * 133 + ff] : (ff == F ? 1.0f : 0.0f);
        g_Y[(size_t)ff * NN + i0 + i] = __float2half(v);
    }
}

// ============================================================================
// Kernel 2 (main): dual masked GEMM, shared-B, software pipelined.
//   A1[i,j] = adj * (s_i+s_j>0)  * e^{s_j}      (fp16)
//   A2[i,j] = adj * (s_i+s_j<=0) * e^{0.2 s_j}  (fp16)
//   D1 = A1@B, D2 = A2@B  (B = [Wh^T ; ones-row]); col 128 = denominators
//   u = e^{s_i} D1 + e^{0.2 s_i} D2 ; out = LN(u[:,:128] / u[:,128])
// ============================================================================
__global__ __launch_bounds__(256, 1) void gat_kernel(const int*   __restrict__ adj,
                                                     const float* __restrict__ gamma,
                                                     const float* __restrict__ beta,
                                                     float*       __restrict__ out) {
    extern __shared__ char smem[];
    const uint32_t sb = smem_u32(smem);

    const int t    = threadIdx.x;
    const int lane = t & 31;
    const int wid  = t >> 5;
    const int ms   = wid & 3;
    const int nh   = wid >> 2;
    const int i0   = blockIdx.x * MT;

    float* e1s = (float*)(smem + OFF_E1);
    float* e2s = (float*)(smem + OFF_E2);
    float* gms = (float*)(smem + OFF_GM);
    float* bts = (float*)(smem + OFF_BT);

    if (t < 64) { e1s[t] = g_e1[i0 + t]; e2s[t] = g_e2[i0 + t]; }
    if (t < 128) { gms[t] = gamma[t]; bts[t] = beta[t]; }

    float acc1[9][4], acc2[9][4];
#pragma unroll
    for (int n = 0; n < 9; n++)
#pragma unroll
        for (int k = 0; k < 4; k++) { acc1[n][k] = 0.f; acc2[n][k] = 0.f; }

    // build-phase indices: 4 threads/row, each covers a 32-col span
    const int brow  = t >> 2;
    const int q     = t & 3;
    const int jbase = q * 32;
    const __half2 si2 = __half2half2(g_sh[i0 + brow]);
    const __half2 z2  = __float2half2_rn(0.f);

    // mma-phase addresses
    const uint32_t rA    = (uint32_t)(ms * 16 + (lane & 15));
    const uint32_t aOff  = rA * TSTR + (((lane >> 4) & 1) * 8) * 2;
    const uint32_t kBoff = (((lane >> 3) & 1) * 8) * 2;
    uint32_t nB[4];
#pragma unroll
    for (int np = 0; np < 4; np++)
        nB[np] = (uint32_t)(nh * 72 + np * 16 + ((lane >> 4) & 1) * 8 + (lane & 7));
    const uint32_t n8 = (uint32_t)(64 + (lane & 7));

    char* smemc = smem;

    auto stageY = [&](int c, int bsel) {
        const uint32_t bufb = sb + bsel * BUFSZ;
        const __half* y = g_Y + c * KC;
        for (int idx = t; idx < NF * 16; idx += 256) {
            int fr = idx >> 4, c16 = idx & 15;
            cpasync16(bufb + SY + fr * TSTR + c16 * 16,
                      (const char*)(y + (size_t)fr * NN) + c16 * 16);
        }
        cpasync_commit();
    };

    auto buildI = [&](const int4* av, int c, int bsel) {
        const int j0 = c * KC;
        char* pdst = smemc + bsel * BUFSZ + SP + brow * TSTR + jbase * 2;
        char* qdst = smemc + bsel * BUFSZ + SQ + brow * TSTR + jbase * 2;
        const uint32_t* sjp = (const uint32_t*)(g_sh   + j0 + jbase);
        const uint32_t* e1p = (const uint32_t*)(g_ej1h + j0 + jbase);
        const uint32_t* e2p = (const uint32_t*)(g_ej2h + j0 + jbase);
#pragma unroll
        for (int k = 0; k < 8; k++) {
            int4 v = av[k];
            uint32_t m01 = __byte_perm((uint32_t)v.x, (uint32_t)v.y, 0x5410) * 0xFFFFu;
            uint32_t m23 = __byte_perm((uint32_t)v.z, (uint32_t)v.w, 0x5410) * 0xFFFFu;
            __half2 s0 = __hadd2(si2, u2h(__ldg(&sjp[2 * k])));
            __half2 s1 = __hadd2(si2, u2h(__ldg(&sjp[2 * k + 1])));
            __half2 g0 = __hgt2(s0, z2), g1 = __hgt2(s1, z2);
            __half2 c0 = __hle2(s0, z2), c1 = __hle2(s1, z2);
            uint32_t A1a = h2u(__hmul2(u2h(__ldg(&e1p[2 * k])),     g0)) & m01;
            uint32_t A1b = h2u(__hmul2(u2h(__ldg(&e1p[2 * k + 1])), g1)) & m23;
            uint32_t A2a = h2u(__hmul2(u2h(__ldg(&e2p[2 * k])),     c0)) & m01;
            uint32_t A2b = h2u(__hmul2(u2h(__ldg(&e2p[2 * k + 1])), c1)) & m23;
            *(uint2*)(pdst + 8 * k) = make_uint2(A1a, A1b);
            *(uint2*)(qdst + 8 * k) = make_uint2(A2a, A2b);
        }
    };

    auto mmaPhase = [&](int bsel) {
        const uint32_t bufb = sb + bsel * BUFSZ;
#pragma unroll 1
        for (int ks = 0; ks < 8; ks++) {
            const uint32_t kb = ks * 32;
            uint32_t a1[4], a2[4], b[4];
            ldsm4(a1, bufb + SP + aOff + kb);
            ldsm4(a2, bufb + SQ + aOff + kb);
#pragma unroll
            for (int np = 0; np < 4; np++) {
                ldsm4(b, bufb + SY + nB[np] * TSTR + kb + kBoff);
                mma16816(acc1[2 * np],     a1, b[0], b[1]);
                mma16816(acc1[2 * np + 1], a1, b[2], b[3]);
                mma16816(acc2[2 * np],     a2, b[0], b[1]);
                mma16816(acc2[2 * np + 1], a2, b[2], b[3]);
            }
            if (nh == 0) {
                ldsm2(b, bufb + SY + n8 * TSTR + kb + kBoff);
                mma16816(acc1[8], a1, b[0], b[1]);
                mma16816(acc2[8], a2, b[0], b[1]);
            }
        }
    };

    // ---- prologue: chunk 0 ----
    {
        stageY(0, 0);
        int4 av[8];
        const int4* ap = (const int4*)(adj + (size_t)(i0 + brow) * NN + jbase);
#pragma unroll
        for (int k = 0; k < 8; k++) av[k] = __ldg(&ap[k]);
        buildI(av, 0, 0);
        cpasync_wait0();
    }
    __syncthreads();

    // ---- main pipelined loop ----
    for (int c = 0; c < NCHUNK; c++) {
        const int b = c & 1;
        int4 av[8];
        const bool pf = (c + 1 < NCHUNK);
        if (pf) {
            const int4* ap = (const int4*)(adj + (size_t)(i0 + brow) * NN +
                                           (c + 1) * KC + jbase);
#pragma unroll
            for (int k = 0; k < 8; k++) av[k] = __ldg(&ap[k]);
            stageY(c + 1, b ^ 1);
        }
        mmaPhase(b);
        if (pf) buildI(av, c + 1, b ^ 1);
        cpasync_wait0();
        __syncthreads();
    }

    // ---- stage u = e1*D1 + e2*D2 (overlays tile buffers) ----
    float* u = (float*)smem;
    {
        const int r0 = ms * 16 + (lane >> 2);
        const int r1 = r0 + 8;
        const int cb = nh * 72 + (lane & 3) * 2;
        const float a10 = e1s[r0], a20 = e2s[r0];
        const float a11 = e1s[r1], a21 = e2s[r1];
        const int NTN = (nh == 0) ? 9 : 8;
#pragma unroll
        for (int nt = 0; nt < 9; nt++) {
            if (nt >= NTN) break;
            int cc = cb + nt * 8;
            float2 v0, v1;
            v0.x = a10 * acc1[nt][0] + a20 * acc2[nt][0];
            v0.y = a10 * acc1[nt][1] + a20 * acc2[nt][1];
            v1.x = a11 * acc1[nt][2] + a21 * acc2[nt][2];
            v1.y = a11 * acc1[nt][3] + a21 * acc2[nt][3];
            *(float2*)&u[r0 * USTR + cc] = v0;
            *(float2*)&u[r1 * USTR + cc] = v1;
        }
    }
    __syncthreads();

    // ---- LayerNorm: 4 threads per row ----
    {
        const int row = t >> 2;
        const int qq  = t & 3;
        const float* ur = u + row * USTR;
        const float inv = 1.0f / ur[128];
        float sm = 0.f, sq = 0.f;
        float4 vv[8];
#pragma unroll
        for (int w = 0; w < 8; w++) {
            float4 v = *(const float4*)&ur[qq * 32 + w * 4];
            v.x *= inv; v.y *= inv; v.z *= inv; v.w *= inv;
            vv[w] = v;
            sm += v.x + v.y + v.z + v.w;
            sq += v.x * v.x + v.y * v.y + v.z * v.z + v.w * v.w;
        }
#pragma unroll
        for (int off = 1; off <= 2; off <<= 1) {
            sm += __shfl_xor_sync(0xffffffffu, sm, off);
            sq += __shfl_xor_sync(0xffffffffu, sq, off);
        }
        const float mean = sm * (1.0f / F);
        const float var  = sq * (1.0f / F) - mean * mean;
        const float rstd = rsqrtf(var + 1e-5f);
        float* orow = out + (size_t)(i0 + row) * F + qq * 32;
#pragma unroll
        for (int w = 0; w < 8; w++) {
            int fb = qq * 32 + w * 4;
            float4 o;
            o.x = (vv[w].x - mean) * rstd * gms[fb + 0] + bts[fb + 0];
            o.y = (vv[w].y - mean) * rstd * gms[fb + 1] + bts[fb + 1];
            o.z = (vv[w].z - mean) * rstd * gms[fb + 2] + bts[fb + 2];
            o.w = (vv[w].w - mean) * rstd * gms[fb + 3] + bts[fb + 3];
            *(float4*)&orow[w * 4] = o;
        }
    }
}

// ============================================================================
// Launch: inputs in metadata order: h, adj, W, a, gamma, beta
// ============================================================================
extern "C" void kernel_launch(void* const* d_in, const int* in_sizes, int n_in,
                              void* d_out, int out_size) {
    const float* h     = (const float*)d_in[0];
    const int*   adj   = (const int*)  d_in[1];
    const float* W     = (const float*)d_in[2];
    const float* a     = (const float*)d_in[3];
    const float* gamma = (const float*)d_in[4];
    const float* beta  = (const float*)d_in[5];
    float* out = (float*)d_out;

    cudaFuncSetAttribute(prep_kernel, cudaFuncAttributeMaxDynamicSharedMemorySize,
                         P_TOT);
    cudaFuncSetAttribute(gat_kernel, cudaFuncAttributeMaxDynamicSharedMemorySize,
                         SMEM_TOT);

    prep_kernel<<<NN / 32, 256, P_TOT>>>(h, W, a);
    gat_kernel<<<NN / MT, 256, SMEM_TOT>>>(adj, gamma, beta, out);
}

// round 8
// speedup vs baseline: 7.8944x; 1.0699x over previous
#include <cuda_runtime.h>
#include <cuda_fp16.h>
#include <cstdint>

// ============================================================================
// Problem constants
// ============================================================================
#define NN    8192
#define IN_F  256
#define F     128          // OUT_F
#define MT    64           // rows per CTA (gat kernel)
#define KC    128          // j-chunk
#define NCHH  32           // chunks per CTA (j-half split)
#define NF    136          // B rows: 128 features + ones row (128) + zero pad
#define USTRD 140          // partial-u row stride (floats)

// ============================================================================
// Scratch globals (no cudaMalloc) — 16B aligned for u32 / cp.async access
// ============================================================================
__device__ __align__(16) __half g_sh[NN];       // fp16(s)
__device__ __align__(16) float  g_e1[NN];       // exp(s)
__device__ __align__(16) float  g_e2[NN];       // exp(0.2 s)
__device__ __align__(16) __half g_ej1h[NN];     // fp16(exp(s))
__device__ __align__(16) __half g_ej2h[NN];     // fp16(exp(0.2 s))
__device__ __align__(16) __half g_Y[NF * NN];   // [f][j] fp16 Wh^T (+ones row)
__device__ __align__(16) float  g_u[2 * NN * USTRD];  // per-j-half partial u

// ============================================================================
// SMEM layout (gat): blocked SW128 tiles, fully double buffered
//   A tile: 64 rows x 128 k f16, 2 k-blocks of 64r..  rows 128 B  -> 16384 B
//   Y tile: 136 rows x 128 k f16, 2 k-blocks (stride 17408)       -> 34816 B
// ============================================================================
#define ABY   16384
#define YBY   34816
#define SA1(b) ((b) * ABY)              // 0 / 16384
#define SA2(b) (32768 + (b) * ABY)      // 32768 / 49152
#define SYB(b) (65536 + (b) * YBY)      // 65536 / 100352
#define SMEM_TOT (65536 + 2 * YBY)      // 135168

// ============================================================================
// PTX helpers (base sm_100 legal)
// ============================================================================
__device__ __forceinline__ uint32_t smem_u32(const void* p) {
    uint32_t a;
    asm("{ .reg .u64 t; cvta.to.shared.u64 t, %1; cvt.u32.u64 %0, t; }"
        : "=r"(a) : "l"(p));
    return a;
}
__device__ __forceinline__ void ldsm4(uint32_t* r, uint32_t addr) {
    asm volatile("ldmatrix.sync.aligned.m8n8.x4.shared.b16 {%0,%1,%2,%3}, [%4];"
                 : "=r"(r[0]), "=r"(r[1]), "=r"(r[2]), "=r"(r[3]) : "r"(addr));
}
__device__ __forceinline__ void ldsm2(uint32_t* r, uint32_t addr) {
    asm volatile("ldmatrix.sync.aligned.m8n8.x2.shared.b16 {%0,%1}, [%2];"
                 : "=r"(r[0]), "=r"(r[1]) : "r"(addr));
}
__device__ __forceinline__ void mma16816(float* d, const uint32_t* a,
                                         uint32_t b0, uint32_t b1) {
    asm volatile(
        "mma.sync.aligned.m16n8k16.row.col.f32.f16.f16.f32 "
        "{%0,%1,%2,%3},{%4,%5,%6,%7},{%8,%9},{%0,%1,%2,%3};"
        : "+f"(d[0]), "+f"(d[1]), "+f"(d[2]), "+f"(d[3])
        : "r"(a[0]), "r"(a[1]), "r"(a[2]), "r"(a[3]), "r"(b0), "r"(b1));
}
__device__ __forceinline__ void cpasync16(uint32_t dst, const void* src) {
    asm volatile("cp.async.cg.shared.global [%0], [%1], 16;" :: "r"(dst), "l"(src)
                 : "memory");
}
__device__ __forceinline__ void cpasync_commit() {
    asm volatile("cp.async.commit_group;" ::: "memory");
}
__device__ __forceinline__ void cpasync_wait0() {
    asm volatile("cp.async.wait_group 0;" ::: "memory");
}
__device__ __forceinline__ uint32_t h2u(__half2 v) {
    union { __half2 h; uint32_t u; } x; x.h = v; return x.u;
}
__device__ __forceinline__ __half2 u2h(uint32_t v) {
    union { __half2 h; uint32_t u; } x; x.u = v; return x.h;
}

// ============================================================================
// Kernel 1 (fused prep): Wh = h @ W^T ; s = Wh @ a^T ; scalars ; Y (transposed)
// (unchanged from Round 7 — known-good)
// ============================================================================
#define P_HS   0                               // hs  [64][36]  f32
#define P_WS   9216                            // Ws  [128][65] f32
#define P_WHS  (P_WS + 33280)                  // whs [32][133] f32
#define P_A    (P_WHS + 17024)
#define P_TOT  (P_A + 512)

__global__ __launch_bounds__(256) void prep_kernel(const float* __restrict__ h,
                                                   const float* __restrict__ W,
                                                   const float* __restrict__ a) {
    extern __shared__ char psm[];
    float* hs  = (float*)(psm + P_HS);
    float* Ws  = (float*)(psm + P_WS);
    float* whs = (float*)(psm + P_WHS);
    float* as_ = (float*)(psm + P_A);

    const int t  = threadIdx.x;
    const int i0 = blockIdx.x * 32;
    const int f  = t & 127;
    const int hf = t >> 7;

    if (t < 128) as_[t] = a[t];

    float acc[16];
#pragma unroll
    for (int i = 0; i < 16; i++) acc[i] = 0.f;

    for (int kb = 0; kb < IN_F; kb += 64) {
        __syncthreads();
        for (int idx = t; idx < 32 * 64; idx += 256) {
            int i = idx >> 6, kk = idx & 63;
            hs[kk * 36 + i] = h[(size_t)(i0 + i) * IN_F + kb + kk];
        }
        for (int idx = t; idx < 128 * 64; idx += 256) {
            int ff = idx >> 6, kk = idx & 63;
            Ws[ff * 65 + kk] = W[(size_t)ff * IN_F + kb + kk];
        }
        __syncthreads();
#pragma unroll 4
        for (int kk = 0; kk < 64; kk++) {
            float wv = Ws[f * 65 + kk];
            const float* hv = &hs[kk * 36 + hf * 16];
#pragma unroll
            for (int i = 0; i < 16; i += 4) {
                float4 v = *(const float4*)&hv[i];
                acc[i + 0] = fmaf(wv, v.x, acc[i + 0]);
                acc[i + 1] = fmaf(wv, v.y, acc[i + 1]);
                acc[i + 2] = fmaf(wv, v.z, acc[i + 2]);
                acc[i + 3] = fmaf(wv, v.w, acc[i + 3]);
            }
        }
    }
    __syncthreads();
#pragma unroll
    for (int i = 0; i < 16; i++)
        whs[(hf * 16 + i) * 133 + f] = acc[i];
    __syncthreads();

    {
        const int wid  = t >> 5;
        const int lane = t & 31;
#pragma unroll
        for (int r = 0; r < 4; r++) {
            int row = wid * 4 + r;
            float sum = 0.f;
#pragma unroll
            for (int m = 0; m < 4; m++)
                sum += whs[row * 133 + lane + 32 * m] * as_[lane + 32 * m];
#pragma unroll
            for (int off = 16; off; off >>= 1)
                sum += __shfl_xor_sync(0xffffffffu, sum, off);
            if (lane == 0) {
                float e1 = __expf(sum);
                float e2 = __expf(0.2f * sum);
                g_sh[i0 + row]   = __float2half(sum);
                g_e1[i0 + row]   = e1;
                g_e2[i0 + row]   = e2;
                g_ej1h[i0 + row] = __float2half(e1);
                g_ej2h[i0 + row] = __float2half(e2);
            }
        }
    }

    for (int idx = t; idx < NF * 32; idx += 256) {
        int ff = idx >> 5, i = idx & 31;
        float v = (ff < F) ? whs[i * 133 + ff] : (ff == F ? 1.0f : 0.0f);
        g_Y[(size_t)ff * NN + i0 + i] = __float2half(v);
    }
}

// ============================================================================
// Kernel 2 (main): dual masked GEMM, swizzled blocked tiles, 512 threads,
// j-split partials. grid = 256: bid&127 -> row tile, bid>>7 -> j half.
// ============================================================================
__global__ __launch_bounds__(512, 1) void gat_kernel(const int* __restrict__ adj) {
    extern __shared__ char smem[];
    const uint32_t sb = smem_u32(smem);

    const int t    = threadIdx.x;
    const int lane = t & 31;
    const int wid  = t >> 5;
    const int ms   = wid & 3;     // m slice (16 rows)
    const int nq   = wid >> 2;    // n quarter
    const int rt   = blockIdx.x & 127;
    const int jh   = blockIdx.x >> 7;
    const int i0   = rt * MT;
    const int jbase0 = jh * (NN / 2);

    // accumulators: nq<3 -> 4 tiles, nq==3 -> 5 (incl. denominator col 128)
    const int NT = (nq == 3) ? 5 : 4;
    float acc1[5][4], acc2[5][4];
#pragma unroll
    for (int n = 0; n < 5; n++)
#pragma unroll
        for (int k = 0; k < 4; k++) { acc1[n][k] = 0.f; acc2[n][k] = 0.f; }

    // ---- build-phase indices: 8 threads/row, 16 j each ----
    const int brow = t >> 3;
    const int jb8  = (t & 7) * 16;
    const int jbyte0 = jb8 * 2;                    // 0..224 step 32
    const uint32_t bldoff = (uint32_t)(((jbyte0 >> 7) << 13) + brow * 128);
    const uint32_t bswx   = (uint32_t)((brow & 7) << 4);
    const uint32_t binner = (uint32_t)(jbyte0 & 127);
    const __half2 si2 = __half2half2(g_sh[i0 + brow]);
    const __half2 z2  = __float2half2_rn(0.f);

    // ---- mma-phase constants ----
    const uint32_t rA   = (uint32_t)(ms * 16 + (lane & 15));
    const uint32_t rAoff = rA * 128;
    const uint32_t swxA  = (rA & 7) << 4;
    const int khA = ((lane >> 4) & 1) * 8;
    const int khB = ((lane >> 3) & 1) * 8;
    uint32_t fOff[2], fSwx[2];
#pragma unroll
    for (int np = 0; np < 2; np++) {
        uint32_t fidx = (uint32_t)(nq * 32 + np * 16 + ((lane >> 4) & 1) * 8 + (lane & 7));
        fOff[np] = fidx * 128;
        fSwx[np] = (fidx & 7) << 4;
    }
    const uint32_t f3idx = (uint32_t)(128 + (lane & 7));
    const uint32_t f3Off = f3idx * 128;
    const uint32_t f3Swx = (f3idx & 7) << 4;

    auto stageY = [&](int jc, int bsel) {   // jc = global chunk j base (halves)
        const uint32_t yb = sb + SYB(bsel);
        const char* ysrc = (const char*)g_Y + (size_t)jc * 2;
        for (int idx = t; idx < NF * 16; idx += 512) {
            int fr = idx >> 4, c = idx & 15;
            int blk = c >> 3, cc = c & 7;
            uint32_t dst = yb + blk * 17408 + fr * 128 + ((cc * 16) ^ ((fr & 7) << 4));
            cpasync16(dst, ysrc + (size_t)fr * (NN * 2) + c * 16);
        }
        cpasync_commit();
    };

    auto buildI = [&](const int4* av, int jc, int bsel) {
        const uint32_t* sjp = (const uint32_t*)(g_sh   + jc + jb8);
        const uint32_t* e1p = (const uint32_t*)(g_ej1h + jc + jb8);
        const uint32_t* e2p = (const uint32_t*)(g_ej2h + jc + jb8);
        uint32_t a1w[8], a2w[8];
#pragma unroll
        for (int p = 0; p < 4; p++) {
            int4 v = av[p];
            uint32_t m01 = __byte_perm((uint32_t)v.x, (uint32_t)v.y, 0x5410) * 0xFFFFu;
            uint32_t m23 = __byte_perm((uint32_t)v.z, (uint32_t)v.w, 0x5410) * 0xFFFFu;
            __half2 s0 = __hadd2(si2, u2h(__ldg(&sjp[2 * p])));
            __half2 s1 = __hadd2(si2, u2h(__ldg(&sjp[2 * p + 1])));
            __half2 g0 = __hgt2(s0, z2), g1 = __hgt2(s1, z2);
            __half2 c0 = __hle2(s0, z2), c1 = __hle2(s1, z2);
            a1w[2 * p]     = h2u(__hmul2(u2h(__ldg(&e1p[2 * p])),     g0)) & m01;
            a1w[2 * p + 1] = h2u(__hmul2(u2h(__ldg(&e1p[2 * p + 1])), g1)) & m23;
            a2w[2 * p]     = h2u(__hmul2(u2h(__ldg(&e2p[2 * p])),     c0)) & m01;
            a2w[2 * p + 1] = h2u(__hmul2(u2h(__ldg(&e2p[2 * p + 1])), c1)) & m23;
        }
        char* p1 = smem + SA1(bsel) + bldoff;
        char* p2 = smem + SA2(bsel) + bldoff;
#pragma unroll
        for (int qq = 0; qq < 2; qq++) {
            uint32_t o = (binner + 16 * qq) ^ bswx;
            *(uint4*)(p1 + o) = make_uint4(a1w[4 * qq], a1w[4 * qq + 1],
                                           a1w[4 * qq + 2], a1w[4 * qq + 3]);
            *(uint4*)(p2 + o) = make_uint4(a2w[4 * qq], a2w[4 * qq + 1],
                                           a2w[4 * qq + 2], a2w[4 * qq + 3]);
        }
    };

    auto mmaPhase = [&](int bsel) {
        const uint32_t a1b = sb + SA1(bsel) + rAoff;
        const uint32_t a2b = sb + SA2(bsel) + rAoff;
        const uint32_t yb  = sb + SYB(bsel);
#pragma unroll 1
        for (int ks = 0; ks < 8; ks++) {
            const int kA = ks * 16 + khA;
            const uint32_t aoff = ((uint32_t)(kA >> 6) << 13) + (((uint32_t)(kA & 63) * 2) ^ swxA);
            const int kB = ks * 16 + khB;
            const uint32_t bblk = (uint32_t)(kB >> 6) * 17408;
            const uint32_t bkin = (uint32_t)(kB & 63) * 2;
            uint32_t a1[4], a2[4], b[4];
            ldsm4(a1, a1b + aoff);
            ldsm4(a2, a2b + aoff);
#pragma unroll
            for (int np = 0; np < 2; np++) {
                ldsm4(b, yb + bblk + fOff[np] + (bkin ^ fSwx[np]));
                mma16816(acc1[2 * np],     a1, b[0], b[1]);
                mma16816(acc1[2 * np + 1], a1, b[2], b[3]);
                mma16816(acc2[2 * np],     a2, b[0], b[1]);
                mma16816(acc2[2 * np + 1], a2, b[2], b[3]);
            }
            if (nq == 3) {
                ldsm2(b, yb + bblk + f3Off + (bkin ^ f3Swx));
                mma16816(acc1[4], a1, b[0], b[1]);
                mma16816(acc2[4], a2, b[0], b[1]);
            }
        }
    };

    // ---- prologue ----
    {
        stageY(jbase0, 0);
        int4 av[4];
        const int4* ap = (const int4*)(adj + (size_t)(i0 + brow) * NN + jbase0 + jb8);
#pragma unroll
        for (int p = 0; p < 4; p++) av[p] = __ldg(&ap[p]);
        buildI(av, jbase0, 0);
        cpasync_wait0();
    }
    __syncthreads();

    // ---- pipelined main loop ----
    for (int c = 0; c < NCHH; c++) {
        const int b = c & 1;
        int4 av[4];
        const bool pf = (c + 1 < NCHH);
        const int jcn = jbase0 + (c + 1) * KC;
        if (pf) {
            const int4* ap = (const int4*)(adj + (size_t)(i0 + brow) * NN + jcn + jb8);
#pragma unroll
            for (int p = 0; p < 4; p++) av[p] = __ldg(&ap[p]);
            stageY(jcn, b ^ 1);
        }
        mmaPhase(b);
        if (pf) buildI(av, jcn, b ^ 1);
        cpasync_wait0();
        __syncthreads();
    }

    // ---- write partial u = e1_i*D1 + e2_i*D2 (row scaling is linear) ----
    {
        float* up = g_u + (size_t)jh * (NN * USTRD) + (size_t)i0 * USTRD;
        const int r0 = ms * 16 + (lane >> 2);
        const int r1 = r0 + 8;
        const float a10 = __ldg(&g_e1[i0 + r0]), a20 = __ldg(&g_e2[i0 + r0]);
        const float a11 = __ldg(&g_e1[i0 + r1]), a21 = __ldg(&g_e2[i0 + r1]);
        const int cb = nq * 32 + (lane & 3) * 2;
#pragma unroll
        for (int nt = 0; nt < 5; nt++) {
            if (nt >= NT) break;
            int col = cb + nt * 8;
            float2 v0, v1;
            v0.x = a10 * acc1[nt][0] + a20 * acc2[nt][0];
            v0.y = a10 * acc1[nt][1] + a20 * acc2[nt][1];
            v1.x = a11 * acc1[nt][2] + a21 * acc2[nt][2];
            v1.y = a11 * acc1[nt][3] + a21 * acc2[nt][3];
            *(float2*)&up[(size_t)r0 * USTRD + col] = v0;
            *(float2*)&up[(size_t)r1 * USTRD + col] = v1;
        }
    }
}

// ============================================================================
// Kernel 3: combine j-half partials, softmax-normalize, LayerNorm. warp/row.
// ============================================================================
__global__ __launch_bounds__(256) void combine_kernel(const float* __restrict__ gamma,
                                                      const float* __restrict__ beta,
                                                      float* __restrict__ out) {
    const int t    = threadIdx.x;
    const int lane = t & 31;
    const int wid  = t >> 5;
    const int row  = blockIdx.x * 8 + wid;

    const float* u0 = g_u + (size_t)row * USTRD;
    const float* u1 = g_u + (size_t)NN * USTRD + (size_t)row * USTRD;

    const float den = u0[128] + u1[128];
    const float inv = 1.0f / den;

    const int c4 = lane * 4;
    float4 p0 = *(const float4*)&u0[c4];
    float4 p1 = *(const float4*)&u1[c4];
    float4 v;
    v.x = (p0.x + p1.x) * inv;
    v.y = (p0.y + p1.y) * inv;
    v.z = (p0.z + p1.z) * inv;
    v.w = (p0.w + p1.w) * inv;

    float sm = v.x + v.y + v.z + v.w;
    float sq = v.x * v.x + v.y * v.y + v.z * v.z + v.w * v.w;
#pragma unroll
    for (int off = 16; off; off >>= 1) {
        sm += __shfl_xor_sync(0xffffffffu, sm, off);
        sq += __shfl_xor_sync(0xffffffffu, sq, off);
    }
    const float mean = sm * (1.0f / F);
    const float var  = sq * (1.0f / F) - mean * mean;
    const float rstd = rsqrtf(var + 1e-5f);

    float4 gm = *(const float4*)&gamma[c4];
    float4 bt = *(const float4*)&beta[c4];
    float4 o;
    o.x = (v.x - mean) * rstd * gm.x + bt.x;
    o.y = (v.y - mean) * rstd * gm.y + bt.y;
    o.z = (v.z - mean) * rstd * gm.z + bt.z;
    o.w = (v.w - mean) * rstd * gm.w + bt.w;
    *(float4*)&out[(size_t)row * F + c4] = o;
}

// ============================================================================
// Launch: inputs in metadata order: h, adj, W, a, gamma, beta
// ============================================================================
extern "C" void kernel_launch(void* const* d_in, const int* in_sizes, int n_in,
                              void* d_out, int out_size) {
    const float* h     = (const float*)d_in[0];
    const int*   adj   = (const int*)  d_in[1];
    const float* W     = (const float*)d_in[2];
    const float* a     = (const float*)d_in[3];
    const float* gamma = (const float*)d_in[4];
    const float* beta  = (const float*)d_in[5];
    float* out = (float*)d_out;

    cudaFuncSetAttribute(prep_kernel, cudaFuncAttributeMaxDynamicSharedMemorySize,
                         P_TOT);
    cudaFuncSetAttribute(gat_kernel, cudaFuncAttributeMaxDynamicSharedMemorySize,
                         SMEM_TOT);

    prep_kernel<<<NN / 32, 256, P_TOT>>>(h, W, a);
    gat_kernel<<<256, 512, SMEM_TOT>>>(adj);
    combine_kernel<<<NN / 8, 256>>>(gamma, beta, out);
}